// round 2
// baseline (speedup 1.0000x reference)
#include <cuda_runtime.h>
#include <cuda_bf16.h>
#include <stdint.h>

// HexCrop: out[b][c][u][v] = (valid ? in[b][c][cu+u-CC][cv+v-CC] : 0) * (mask ? crop_mask[u][v] : 1)
// plus crop_mask itself appended at out[B*C*K*K ...].
//
// B=256, C=256, H=W=64, K=31, CC=15. Pure streaming gather: DRAM-bound.
// Each block handles CPB channels of one batch (same center), amortizing
// mask staging / center load and raising per-thread MLP via channel unroll.

#define ENV 64
#define K   31
#define CC  15
#define KK  (K * K)   // 961
#define NTHREADS 256
#define CPB 4         // channels per block

__global__ __launch_bounds__(NTHREADS, 8)
void hexcrop_kernel(const float* __restrict__ in,          // [B,C,64,64]
                    const int*   __restrict__ centers,     // [B,2] int32
                    const float* __restrict__ crop_mask,   // [31,31]
                    const int*   __restrict__ mask_flag,   // scalar (device)
                    float*       __restrict__ out)         // [B,C,31,31] + [31,31]
{
    __shared__ float smask[KK];
    __shared__ int s_cu, s_cv, s_use_mask;

    const int tid = threadIdx.x;
    const int blk = blockIdx.x;                 // over B*C/CPB
    const int bc0 = blk * CPB;                  // first channel index (b*C + c)
    const int b   = bc0 >> 8;                   // C == 256

    // Stage mask into shared memory (reused by CPB channels).
    #pragma unroll
    for (int i = tid; i < KK; i += NTHREADS)
        smask[i] = crop_mask[i];

    if (tid == 0) {
        s_cu = centers[2 * b + 0];
        s_cv = centers[2 * b + 1];
        // nonzero test: works for int32(1), low word of int64(1), float32(1.0)
        s_use_mask = (mask_flag != nullptr && mask_flag[0] != 0) ? 1 : 0;
    }
    __syncthreads();

    const int cu = s_cu;
    const int cv = s_cv;
    const int use_mask = s_use_mask;

    const float* src = in  + (size_t)bc0 * (ENV * ENV);
    float*       dst = out + (size_t)bc0 * KK;

    // 961 tile positions; for each, gather CPB independent channels.
    for (int i = tid; i < KK; i += NTHREADS) {
        const int u = i / K;                     // mul-shift, cheap
        const int v = i - u * K;
        const int row = cu + u - CC;
        const int col = cv + v - CC;
        const bool valid = ((unsigned)row < ENV) & ((unsigned)col < ENV);
        const int soff = row * ENV + col;
        const float m = use_mask ? smask[i] : 1.0f;

        float vals[CPB];
        #pragma unroll
        for (int c = 0; c < CPB; ++c)           // independent loads -> MLP
            vals[c] = valid ? __ldg(src + (size_t)c * (ENV * ENV) + soff) : 0.0f;

        #pragma unroll
        for (int c = 0; c < CPB; ++c)
            dst[(size_t)c * KK + i] = vals[c] * m;
    }

    // Block 0 writes the raw mask tail (second tuple element).
    if (blk == 0) {
        float* tail = out + (size_t)gridDim.x * CPB * KK;
        #pragma unroll
        for (int i = tid; i < KK; i += NTHREADS)
            tail[i] = smask[i];
    }
}

extern "C" void kernel_launch(void* const* d_in, const int* in_sizes, int n_in,
                              void* d_out, int out_size)
{
    const float* in       = (const float*)d_in[0];   // input_tensor [256,256,64,64] f32
    const int*   centers  = (const int*)  d_in[1];   // center_positions [256,2] i32
    const float* cmask    = (const float*)d_in[2];   // crop_mask [31,31] f32
    const int*   maskflag = (n_in > 3) ? (const int*)d_in[3] : nullptr;

    const int B = in_sizes[1] / 2;                    // 256
    const int C = in_sizes[0] / (B * ENV * ENV);      // 256

    float* out = (float*)d_out;
    hexcrop_kernel<<<(B * C) / CPB, NTHREADS>>>(in, centers, cmask, maskflag, out);
}

// round 4
// speedup vs baseline: 1.3699x; 1.3699x over previous
#include <cuda_runtime.h>
#include <cuda_bf16.h>
#include <stdint.h>

// HexCrop: out[b][c][u][v] = (valid ? in[b][c][cu+u-CC][cv+v-CC] : 0) * (mask ? crop_mask[u][v] : 1)
// plus crop_mask itself appended at out[B*C*K*K ...].
//
// B=256, C=256, H=W=64, K=31, CC=15. DRAM-bound streaming.
// KEY: the hex-FOV crop_mask is ~96% zeros (radius ~6.28 disk x 96.5deg wedge
// in a 31x31 grid). When the mask is applied, masked-out outputs are exactly
// 0.0 independent of the input -> skip those gather loads entirely.
// Read traffic ~252MB -> ~10MB; the 252MB of writes become the floor.
// CPB=8 channels/block amortizes mask staging + center load.

#define ENV 64
#define K   31
#define CC  15
#define KK  (K * K)   // 961
#define NTHREADS 256
#define CPB 8         // channels per block (same batch -> same center)

__global__ __launch_bounds__(NTHREADS, 8)
void hexcrop_kernel(const float* __restrict__ in,          // [B,C,64,64]
                    const int*   __restrict__ centers,     // [B,2] int32
                    const float* __restrict__ crop_mask,   // [31,31]
                    const int*   __restrict__ mask_flag,   // scalar (device)
                    float*       __restrict__ out)         // [B,C,31,31] + [31,31]
{
    __shared__ float smask[KK];
    __shared__ int s_cu, s_cv, s_use_mask;

    const int tid = threadIdx.x;
    const int blk = blockIdx.x;                 // over B*C/CPB
    const int bc0 = blk * CPB;                  // first channel index (b*C + c)
    const int b   = bc0 >> 8;                   // C == 256

    // Stage mask into shared memory (reused by CPB channels).
    #pragma unroll
    for (int i = tid; i < KK; i += NTHREADS)
        smask[i] = crop_mask[i];

    if (tid == 0) {
        s_cu = centers[2 * b + 0];
        s_cv = centers[2 * b + 1];
        // nonzero test: works for int32(1), low word of int64(1), float32(1.0)
        s_use_mask = (mask_flag != nullptr && mask_flag[0] != 0) ? 1 : 0;
    }
    __syncthreads();

    const int cu = s_cu;
    const int cv = s_cv;
    const int use_mask = s_use_mask;

    const float* src = in  + (size_t)bc0 * (ENV * ENV);
    float*       dst = out + (size_t)bc0 * KK;

    // 961 tile positions; for each, gather CPB independent channels —
    // but only where the output can be nonzero.
    for (int i = tid; i < KK; i += NTHREADS) {
        const int u = i / K;
        const int v = i - u * K;
        const int row = cu + u - CC;
        const int col = cv + v - CC;
        const float m = use_mask ? smask[i] : 1.0f;

        // Load only if in-range AND the mask can pass a nonzero through.
        const bool live = ((unsigned)row < ENV) & ((unsigned)col < ENV)
                          & (m != 0.0f);
        const int soff = row * ENV + col;

        float vals[CPB];
        #pragma unroll
        for (int c = 0; c < CPB; ++c)           // independent loads -> MLP
            vals[c] = live ? __ldg(src + (size_t)c * (ENV * ENV) + soff) : 0.0f;

        #pragma unroll
        for (int c = 0; c < CPB; ++c)
            dst[(size_t)c * KK + i] = vals[c] * m;
    }

    // Block 0 writes the raw mask tail (second tuple element).
    if (blk == 0) {
        float* tail = out + (size_t)gridDim.x * CPB * KK;
        #pragma unroll
        for (int i = tid; i < KK; i += NTHREADS)
            tail[i] = smask[i];
    }
}

extern "C" void kernel_launch(void* const* d_in, const int* in_sizes, int n_in,
                              void* d_out, int out_size)
{
    const float* in       = (const float*)d_in[0];   // input_tensor [256,256,64,64] f32
    const int*   centers  = (const int*)  d_in[1];   // center_positions [256,2] i32
    const float* cmask    = (const float*)d_in[2];   // crop_mask [31,31] f32
    const int*   maskflag = (n_in > 3) ? (const int*)d_in[3] : nullptr;

    const int B = in_sizes[1] / 2;                    // 256
    const int C = in_sizes[0] / (B * ENV * ENV);      // 256

    float* out = (float*)d_out;
    hexcrop_kernel<<<(B * C) / CPB, NTHREADS>>>(in, centers, cmask, maskflag, out);
}

// round 8
// speedup vs baseline: 1.6787x; 1.2255x over previous
#include <cuda_runtime.h>
#include <cuda_bf16.h>
#include <stdint.h>

// HexCrop: out[b][c][u][v] = (valid ? in[b][c][cu+u-CC][cv+v-CC] : 0) * (mask ? crop_mask[u][v] : 1)
// plus crop_mask itself appended at out[B*C*K*K ...].
//
// B=256, C=256, H=W=64, K=31, CC=15.
// ~96% of the hex-FOV mask is zero. Strategy: ZERO-FILL the whole output
// region with aligned float4 stores (cheapest stream for the 252MB write
// floor), then FIX UP only the ~35 live positions x CPB channels per block
// with gather+scalar store. Reads ~10MB; fixup double-writes coalesce in L2.

#define ENV 64
#define K   31
#define CC  15
#define KK  (K * K)            // 961
#define NTHREADS 256
#define CPB 8                  // channels per block (same batch, contiguous in out)
#define REGION (CPB * KK)      // 7688 floats; region start is 16B-aligned
#define NVEC (REGION / 4)      // 1922 float4 stores per block
#define MAXLIVE 992            // safe upper bound on live positions

__global__ __launch_bounds__(NTHREADS, 8)
void hexcrop_kernel(const float* __restrict__ in,          // [B,C,64,64]
                    const int*   __restrict__ centers,     // [B,2] int32
                    const float* __restrict__ crop_mask,   // [31,31]
                    const int*   __restrict__ mask_flag,   // scalar (device)
                    float*       __restrict__ out)         // [B,C,31,31] + [31,31]
{
    __shared__ int   s_idx[MAXLIVE];   // live tile position i
    __shared__ int   s_off[MAXLIVE];   // gather offset in src map
    __shared__ float s_mv [MAXLIVE];   // multiplier at that position
    __shared__ int   s_n;              // live count

    const int tid = threadIdx.x;
    const int blk = blockIdx.x;                 // over B*C/CPB
    const int bc0 = blk * CPB;                  // first channel index (b*C + c)
    const int b   = bc0 >> 8;                   // C == 256

    if (tid == 0) s_n = 0;
    __syncthreads();

    const int cu = centers[2 * b + 0];
    const int cv = centers[2 * b + 1];
    const int use_mask = (mask_flag != nullptr && mask_flag[0] != 0) ? 1 : 0;

    // Phase 0: build compact live-position list (~35 entries when mask on).
    // Insertion order is irrelevant: each entry's effect is independent.
    for (int i = tid; i < KK; i += NTHREADS) {
        const int u = i / K;
        const int v = i - u * K;
        const int row = cu + u - CC;
        const int col = cv + v - CC;
        const float m = use_mask ? crop_mask[i] : 1.0f;
        const bool live = ((unsigned)row < ENV) & ((unsigned)col < ENV)
                          & (m != 0.0f);
        if (live) {
            const int p = atomicAdd(&s_n, 1);
            s_idx[p] = i;
            s_off[p] = row * ENV + col;
            s_mv [p] = m;
        }
    }

    float* dst = out + (size_t)bc0 * KK;   // contiguous REGION floats, 16B-aligned

    // Phase A: zero-fill the entire region with aligned float4 stores.
    const float4 z = make_float4(0.f, 0.f, 0.f, 0.f);
    #pragma unroll 8
    for (int t = tid; t < NVEC; t += NTHREADS)
        reinterpret_cast<float4*>(dst)[t] = z;

    __syncthreads();   // fill complete before fixups (cross-thread overlap)

    // Phase B: fix up live positions across all CPB channels.
    // Consecutive threads -> consecutive live positions within one channel
    // (better dst/src locality for the tiny fixup phase).
    const int n = s_n;
    const float* src0 = in + (size_t)bc0 * (ENV * ENV);
    for (int t = tid; t < n * CPB; t += NTHREADS) {
        const int c = t / n;
        const int p = t - c * n;
        const float val = __ldg(src0 + (size_t)c * (ENV * ENV) + s_off[p]) * s_mv[p];
        dst[(size_t)c * KK + s_idx[p]] = val;
    }

    // Block 0 writes the raw mask tail (second tuple element).
    if (blk == 0) {
        float* tail = out + (size_t)gridDim.x * REGION;
        for (int i = tid; i < KK; i += NTHREADS)
            tail[i] = crop_mask[i];
    }
}

extern "C" void kernel_launch(void* const* d_in, const int* in_sizes, int n_in,
                              void* d_out, int out_size)
{
    const float* in       = (const float*)d_in[0];   // input_tensor [256,256,64,64] f32
    const int*   centers  = (const int*)  d_in[1];   // center_positions [256,2] i32
    const float* cmask    = (const float*)d_in[2];   // crop_mask [31,31] f32
    const int*   maskflag = (n_in > 3) ? (const int*)d_in[3] : nullptr;

    const int B = in_sizes[1] / 2;                    // 256
    const int C = in_sizes[0] / (B * ENV * ENV);      // 256

    float* out = (float*)d_out;
    hexcrop_kernel<<<(B * C) / CPB, NTHREADS>>>(in, centers, cmask, maskflag, out);
}